// round 10
// baseline (speedup 1.0000x reference)
#include <cuda_runtime.h>
#include <cuda_bf16.h>
#include <cstdint>

// LSTM(I=13,H=64,T=5)+MLP(64->64 relu ->13), B=262144.
// Round 10: R9 (mma.sync bf16 hi/lo 3-product) + ldmatrix.x4 fragment loads
// + double-buffered A tile (one barrier per step). Z scratch aliases the
// gate-weight region (dead after the recurrence).

#define THREADS 512
#define CTA_ROWS 128
#define WSTR 88     // halves per k-row (176B, odd multiple of 16B -> conflict-free)
#define WSTR32 44
#define ZSTR 72
#define ZSTR32 36

// byte offsets in dynamic smem
#define OFF_WHI   0         // [256][88] bf16 : 45056
#define OFF_WLO   45056
#define OFF_A0HI  90112     // [128][88] bf16 : 22528
#define OFF_A0LO  112640
#define OFF_A1HI  135168
#define OFF_A1LO  157696
#define OFF_W1HI  180224    // [64][88] bf16  : 11264
#define OFF_W1LO  191488
#define OFF_W2HI  202752    // [16][88] bf16  : 2816
#define OFF_W2LO  205568
#define OFF_BC    208384    // float [256]
#define OFF_B1    209408    // float [64]
#define OFF_B2    209664    // float [16]
#define SMEM_BYTES 209728
#define A_LO_DELTA 22528    // A0LO-A0HI == A1LO-A1HI
#define W_LO_DELTA 45056
#define OFF_ZHI   OFF_WHI   // [128][72] bf16 : 18432 (aliases dead gate-W)
#define OFF_ZLO   OFF_WLO

__device__ __forceinline__ void mma16816(float* d,
    uint32_t a0, uint32_t a1, uint32_t a2, uint32_t a3,
    uint32_t b0, uint32_t b1)
{
    asm volatile(
        "mma.sync.aligned.m16n8k16.row.col.f32.bf16.bf16.f32 "
        "{%0,%1,%2,%3}, {%4,%5,%6,%7}, {%8,%9}, {%0,%1,%2,%3};"
        : "+f"(d[0]), "+f"(d[1]), "+f"(d[2]), "+f"(d[3])
        : "r"(a0), "r"(a1), "r"(a2), "r"(a3), "r"(b0), "r"(b1));
}

__device__ __forceinline__ void ldmx4(uint32_t& r0, uint32_t& r1,
                                      uint32_t& r2, uint32_t& r3, uint32_t addr)
{
    asm volatile("ldmatrix.sync.aligned.m8n8.x4.shared.b16 {%0,%1,%2,%3}, [%4];"
        : "=r"(r0), "=r"(r1), "=r"(r2), "=r"(r3) : "r"(addr));
}

__device__ __forceinline__ void bsplit(float v, unsigned short& h, unsigned short& l) {
    __nv_bfloat16 hb = __float2bfloat16(v);
    __nv_bfloat16 lb = __float2bfloat16(v - __bfloat162float(hb));
    h = __bfloat16_as_ushort(hb);
    l = __bfloat16_as_ushort(lb);
}

__device__ __forceinline__ float fsig(float v) {
    return __fdividef(1.0f, 1.0f + __expf(-v));
}
__device__ __forceinline__ float ftanh_(float v) {
    v = fminf(fmaxf(v, -15.0f), 15.0f);
    float e = __expf(-2.0f * v);
    return __fdividef(1.0f - e, 1.0f + e);
}

__device__ __forceinline__ uint32_t smem_u32(const void* p) {
    uint32_t a;
    asm("{ .reg .u64 t; cvta.to.shared.u64 t, %1; cvt.u32.u64 %0, t; }"
        : "=r"(a) : "l"(p));
    return a;
}

extern __shared__ char smem_raw[];

__global__ void __launch_bounds__(THREADS, 1)
lstm_hmma3_kernel(const float* __restrict__ x,
                  const float* __restrict__ W_ih,
                  const float* __restrict__ W_hh,
                  const float* __restrict__ b_ih,
                  const float* __restrict__ b_hh,
                  const float* __restrict__ W1,
                  const float* __restrict__ b1,
                  const float* __restrict__ W2,
                  const float* __restrict__ b2,
                  float* __restrict__ out,
                  int B)
{
    unsigned short* sW_hi  = (unsigned short*)(smem_raw + OFF_WHI);
    unsigned short* sW_lo  = (unsigned short*)(smem_raw + OFF_WLO);
    unsigned short* sW1_hi = (unsigned short*)(smem_raw + OFF_W1HI);
    unsigned short* sW1_lo = (unsigned short*)(smem_raw + OFF_W1LO);
    unsigned short* sW2_hi = (unsigned short*)(smem_raw + OFF_W2HI);
    unsigned short* sW2_lo = (unsigned short*)(smem_raw + OFF_W2LO);
    unsigned short* sZ_hi  = (unsigned short*)(smem_raw + OFF_ZHI);
    unsigned short* sZ_lo  = (unsigned short*)(smem_raw + OFF_ZLO);
    const uint32_t* W2_hi32 = (const uint32_t*)sW2_hi;
    const uint32_t* W2_lo32 = (const uint32_t*)sW2_lo;
    const uint32_t* Z_hi32  = (const uint32_t*)sZ_hi;
    const uint32_t* Z_lo32  = (const uint32_t*)sZ_lo;
    float* s_bc = (float*)(smem_raw + OFF_BC);
    float* s_b1 = (float*)(smem_raw + OFF_B1);
    float* s_b2 = (float*)(smem_raw + OFF_B2);

    const uint32_t sbase = smem_u32(smem_raw);

    const int tid  = threadIdx.x;
    const int lane = tid & 31;
    const int w    = tid >> 5;      // warp 0..15
    const int g    = lane >> 2;     // 0..7
    const int c    = lane & 3;      // 0..3
    const bool odd = (c & 1);
    const int quad = lane >> 3;     // ldmatrix group 0..3
    const int lrow = lane & 7;
    const int rg   = w >> 3;        // row group 0..1 (64 rows each)
    const int cg   = w & 7;         // col group 0..7 (32 gate-cols each)
    const int b0   = blockIdx.x * CTA_ROWS;

    // ---------------- stage weights (bf16 hi/lo) ----------------
    for (int idx = tid; idx < 256 * 80; idx += THREADS) {
        int C = idx / 80, k = idx % 80;
        int R = 64 * (C & 3) + (C >> 2);
        float v = 0.0f;
        if (k < 64)      v = W_hh[R * 64 + k];
        else if (k < 77) v = W_ih[R * 13 + (k - 64)];
        unsigned short h, l; bsplit(v, h, l);
        sW_hi[C * WSTR + k] = h;
        sW_lo[C * WSTR + k] = l;
    }
    for (int idx = tid; idx < 64 * 64; idx += THREADS) {
        int j = idx >> 6, k = idx & 63;
        unsigned short h, l; bsplit(W1[j * 64 + k], h, l);
        sW1_hi[j * WSTR + k] = h;
        sW1_lo[j * WSTR + k] = l;
    }
    for (int idx = tid; idx < 16 * 64; idx += THREADS) {
        int p = idx >> 6, k = idx & 63;
        float v = (p < 13) ? W2[p * 64 + k] : 0.0f;
        unsigned short h, l; bsplit(v, h, l);
        sW2_hi[p * WSTR + k] = h;
        sW2_lo[p * WSTR + k] = l;
    }
    for (int idx = tid; idx < 256; idx += THREADS) {
        int R = 64 * (idx & 3) + (idx >> 2);
        s_bc[idx] = b_ih[R] + b_hh[R];
    }
    if (tid < 64) s_b1[tid] = b1[tid];
    if (tid < 16) s_b2[tid] = (tid < 13) ? b2[tid] : 0.0f;

    // zero BOTH A buffers (h0 = 0; pads k77..79 stay 0 forever)
    {
        uint32_t* A0 = (uint32_t*)(smem_raw + OFF_A0HI);
        for (int idx = tid; idx < 4 * CTA_ROWS * WSTR32; idx += THREADS)
            A0[idx] = 0;
    }
    __syncthreads();

    // x(t=0) into buffer 0 at k = 64+i
    {
        unsigned short* aHi = (unsigned short*)(smem_raw + OFF_A0HI);
        unsigned short* aLo = (unsigned short*)(smem_raw + OFF_A0LO);
        for (int idx = tid; idx < CTA_ROWS * 13; idx += THREADS) {
            int r = idx / 13, i = idx % 13;
            unsigned short h, l; bsplit(x[(size_t)(b0 + r) * 65 + i], h, l);
            aHi[r * WSTR + 64 + i] = h;
            aLo[r * WSTR + 64 + i] = l;
        }
    }

    // per-thread ldmatrix lane addresses
    const uint32_t laneA = (uint32_t)(((rg * 64 + (quad & 1) * 8 + lrow) * WSTR
                                       + (quad >> 1) * 8) * 2);
    const uint32_t laneB = (uint32_t)(((32 * cg + (quad >> 1) * 8 + lrow) * WSTR
                                       + (quad & 1) * 8) * 2);
    const uint32_t aBufHi[2] = {sbase + OFF_A0HI, sbase + OFF_A1HI};
    const uint32_t wGate = sbase + OFF_WHI;

    float creg[16];
#pragma unroll
    for (int i = 0; i < 16; i++) creg[i] = 0.0f;

    __syncthreads();

    // ---------------- 5 recurrent steps (1 barrier each) ----------------
#pragma unroll 1
    for (int t = 0; t < 5; t++) {
        // prefetch x(t+1)
        float xf[4];
        if (t < 4) {
#pragma unroll
            for (int s = 0; s < 4; s++) {
                int idx = tid + s * THREADS;
                if (idx < CTA_ROWS * 13) {
                    int r = idx / 13, i = idx % 13;
                    xf[s] = x[(size_t)(b0 + r) * 65 + (t + 1) * 13 + i];
                }
            }
        }

        const uint32_t aCur = aBufHi[t & 1] + laneA;
        float hv[16];

#pragma unroll
        for (int p = 0; p < 2; p++) {
            float d[4][2][4];
#pragma unroll
            for (int ct = 0; ct < 2; ct++) {
                int C0 = 32 * cg + 16 * p + 8 * ct + 2 * c;
                float bx = s_bc[C0], by = s_bc[C0 + 1];
#pragma unroll
                for (int rt = 0; rt < 4; rt++) {
                    d[rt][ct][0] = bx; d[rt][ct][1] = by;
                    d[rt][ct][2] = bx; d[rt][ct][3] = by;
                }
            }

#pragma unroll
            for (int kc = 0; kc < 5; kc++) {
                uint32_t bAddr = wGate + laneB + p * (16 * WSTR * 2) + kc * 32;
                uint32_t bh0, bh1, bh2, bh3, bl0, bl1, bl2, bl3;
                ldmx4(bh0, bh1, bh2, bh3, bAddr);               // ct0 b0,b1 | ct1 b0,b1
                ldmx4(bl0, bl1, bl2, bl3, bAddr + W_LO_DELTA);
#pragma unroll
                for (int rt = 0; rt < 4; rt++) {
                    uint32_t aAddr = aCur + rt * (16 * WSTR * 2) + kc * 32;
                    uint32_t ah0, ah1, ah2, ah3, al0, al1, al2, al3;
                    ldmx4(ah0, ah1, ah2, ah3, aAddr);
                    ldmx4(al0, al1, al2, al3, aAddr + A_LO_DELTA);
                    mma16816(d[rt][0], ah0, ah1, ah2, ah3, bh0, bh1);
                    mma16816(d[rt][0], ah0, ah1, ah2, ah3, bl0, bl1);
                    mma16816(d[rt][0], al0, al1, al2, al3, bh0, bh1);
                    mma16816(d[rt][1], ah0, ah1, ah2, ah3, bh2, bh3);
                    mma16816(d[rt][1], ah0, ah1, ah2, ah3, bl2, bl3);
                    mma16816(d[rt][1], al0, al1, al2, al3, bh2, bh3);
                }
            }

            // epilogue compute
#pragma unroll
            for (int rt = 0; rt < 4; rt++) {
#pragma unroll
                for (int ct = 0; ct < 2; ct++) {
                    float d0 = d[rt][ct][0], d1 = d[rt][ct][1];
                    float d2 = d[rt][ct][2], d3 = d[rt][ct][3];
                    float e0 = __shfl_xor_sync(0xffffffffu, d0, 1);
                    float e1 = __shfl_xor_sync(0xffffffffu, d1, 1);
                    float e2 = __shfl_xor_sync(0xffffffffu, d2, 1);
                    float e3 = __shfl_xor_sync(0xffffffffu, d3, 1);
                    float gi = odd ? e2 : d0;
                    float gf = odd ? e3 : d1;
                    float gg = odd ? d2 : e0;
                    float go = odd ? d3 : e1;
                    int ci = p * 8 + rt * 2 + ct;
                    float cn = fsig(gf) * creg[ci] + fsig(gi) * ftanh_(gg);
                    creg[ci] = cn;
                    hv[ci] = fsig(go) * ftanh_(cn);
                }
            }
        }

        // write h(t+1) and x(t+1) into the OTHER buffer (no read conflict)
        {
            unsigned short* nHi = (unsigned short*)(smem_raw +
                                    ((t & 1) ? OFF_A0HI : OFF_A1HI));
            unsigned short* nLo = nHi + A_LO_DELTA / 2;
#pragma unroll
            for (int p = 0; p < 2; p++) {
#pragma unroll
                for (int rt = 0; rt < 4; rt++) {
#pragma unroll
                    for (int ct = 0; ct < 2; ct++) {
                        int row = rg * 64 + 16 * rt + g + (odd ? 8 : 0);
                        int n   = 8 * cg + 4 * p + 2 * ct + (c >> 1);
                        unsigned short h, l; bsplit(hv[p * 8 + rt * 2 + ct], h, l);
                        nHi[row * WSTR + n] = h;
                        nLo[row * WSTR + n] = l;
                    }
                }
            }
            if (t < 4) {
#pragma unroll
                for (int s = 0; s < 4; s++) {
                    int idx = tid + s * THREADS;
                    if (idx < CTA_ROWS * 13) {
                        int r = idx / 13, i = idx % 13;
                        unsigned short h, l; bsplit(xf[s], h, l);
                        nHi[r * WSTR + 64 + i] = h;
                        nLo[r * WSTR + 64 + i] = l;
                    }
                }
            }
        }
        __syncthreads();
    }

    // final h lives in buffer 1 (written by step t=4)
    const uint32_t aFin = aBufHi[1] + laneA;

    // ---------------- MLP layer 1 via mma: z = relu(h @ W1^T + b1) ----------------
    {
        const int m_cg = w & 7;      // 8 cols per warp
        // B fragments: 2 x ldmatrix.x4 per hi/lo covers kc0..3
        uint32_t laneB1 = (uint32_t)(((8 * m_cg + lrow) * WSTR + quad * 8) * 2);
        uint32_t b1Addr = sbase + OFF_W1HI + laneB1;
        uint32_t h01[4], h23[4], l01[4], l23[4];
        ldmx4(h01[0], h01[1], h01[2], h01[3], b1Addr);            // kc0 b0,b1 | kc1 b0,b1
        ldmx4(h23[0], h23[1], h23[2], h23[3], b1Addr + 64);       // kc2, kc3
        ldmx4(l01[0], l01[1], l01[2], l01[3], b1Addr + (OFF_W1LO - OFF_W1HI));
        ldmx4(l23[0], l23[1], l23[2], l23[3], b1Addr + (OFF_W1LO - OFF_W1HI) + 64);

        int col0 = 8 * m_cg + 2 * c;
        float dz[4][4];
#pragma unroll
        for (int rt = 0; rt < 4; rt++) {
            dz[rt][0] = s_b1[col0]; dz[rt][1] = s_b1[col0 + 1];
            dz[rt][2] = s_b1[col0]; dz[rt][3] = s_b1[col0 + 1];
        }
#pragma unroll
        for (int kc = 0; kc < 4; kc++) {
            uint32_t wb0 = (kc < 2) ? h01[2 * kc]     : h23[2 * (kc - 2)];
            uint32_t wb1 = (kc < 2) ? h01[2 * kc + 1] : h23[2 * (kc - 2) + 1];
            uint32_t vb0 = (kc < 2) ? l01[2 * kc]     : l23[2 * (kc - 2)];
            uint32_t vb1 = (kc < 2) ? l01[2 * kc + 1] : l23[2 * (kc - 2) + 1];
#pragma unroll
            for (int rt = 0; rt < 4; rt++) {
                uint32_t aAddr = aFin + rt * (16 * WSTR * 2) + kc * 32;
                uint32_t ah0, ah1, ah2, ah3, al0, al1, al2, al3;
                ldmx4(ah0, ah1, ah2, ah3, aAddr);
                ldmx4(al0, al1, al2, al3, aAddr + A_LO_DELTA);
                mma16816(dz[rt], ah0, ah1, ah2, ah3, wb0, wb1);
                mma16816(dz[rt], ah0, ah1, ah2, ah3, vb0, vb1);
                mma16816(dz[rt], al0, al1, al2, al3, wb0, wb1);
            }
        }
        __syncthreads();   // gate-W fully dead before Z (aliased) writes
#pragma unroll
        for (int rt = 0; rt < 4; rt++) {
            int rA = rg * 64 + 16 * rt + g, rB = rA + 8;
            unsigned short h, l;
            bsplit(fmaxf(dz[rt][0], 0.0f), h, l);
            sZ_hi[rA * ZSTR + col0] = h;     sZ_lo[rA * ZSTR + col0] = l;
            bsplit(fmaxf(dz[rt][1], 0.0f), h, l);
            sZ_hi[rA * ZSTR + col0 + 1] = h; sZ_lo[rA * ZSTR + col0 + 1] = l;
            bsplit(fmaxf(dz[rt][2], 0.0f), h, l);
            sZ_hi[rB * ZSTR + col0] = h;     sZ_lo[rB * ZSTR + col0] = l;
            bsplit(fmaxf(dz[rt][3], 0.0f), h, l);
            sZ_hi[rB * ZSTR + col0 + 1] = h; sZ_lo[rB * ZSTR + col0 + 1] = l;
        }
    }
    __syncthreads();

    // ---------------- MLP layer 2 via mma: out = z @ W2^T + b2 ----------------
    {
        const int r2 = w >> 1;       // 0..7 (16 rows)
        const int c2 = w & 1;        // 0..1 (8 cols)
        int colA = 8 * c2 + 2 * c, colB = colA + 1;
        float dd[4];
        dd[0] = s_b2[colA]; dd[1] = s_b2[colB];
        dd[2] = s_b2[colA]; dd[3] = s_b2[colB];
#pragma unroll
        for (int kc = 0; kc < 4; kc++) {
            int widx = (8 * c2 + g) * WSTR32 + 8 * kc + c;
            uint32_t b2h0 = W2_hi32[widx], b2h1 = W2_hi32[widx + 4];
            uint32_t b2l0 = W2_lo32[widx], b2l1 = W2_lo32[widx + 4];
            int r0w = (16 * r2 + g) * ZSTR32 + 8 * kc + c;
            int r1w = r0w + 8 * ZSTR32;
            uint32_t ah0 = Z_hi32[r0w],     ah1 = Z_hi32[r1w];
            uint32_t ah2 = Z_hi32[r0w + 4], ah3 = Z_hi32[r1w + 4];
            uint32_t al0 = Z_lo32[r0w],     al1 = Z_lo32[r1w];
            uint32_t al2 = Z_lo32[r0w + 4], al3 = Z_lo32[r1w + 4];
            mma16816(dd, ah0, ah1, ah2, ah3, b2h0, b2h1);
            mma16816(dd, ah0, ah1, ah2, ah3, b2l0, b2l1);
            mma16816(dd, al0, al1, al2, al3, b2h0, b2h1);
        }
        int rowA = 16 * r2 + g, rowB = rowA + 8;
        if (colA < 13) {
            out[(size_t)(b0 + rowA) * 13 + colA] = dd[0];
            out[(size_t)(b0 + rowB) * 13 + colA] = dd[2];
        }
        if (colB < 13) {
            out[(size_t)(b0 + rowA) * 13 + colB] = dd[1];
            out[(size_t)(b0 + rowB) * 13 + colB] = dd[3];
        }
    }
}

extern "C" void kernel_launch(void* const* d_in, const int* in_sizes, int n_in,
                              void* d_out, int out_size)
{
    const float* x    = (const float*)d_in[0];
    const float* W_ih = (const float*)d_in[1];
    const float* W_hh = (const float*)d_in[2];
    const float* b_ih = (const float*)d_in[3];
    const float* b_hh = (const float*)d_in[4];
    const float* W1   = (const float*)d_in[5];
    const float* b1   = (const float*)d_in[6];
    const float* W2   = (const float*)d_in[7];
    const float* b2   = (const float*)d_in[8];
    float* out = (float*)d_out;

    const int B = in_sizes[0] / 65;

    cudaFuncSetAttribute(lstm_hmma3_kernel,
                         cudaFuncAttributeMaxDynamicSharedMemorySize, SMEM_BYTES);

    const int grid = B / CTA_ROWS;
    lstm_hmma3_kernel<<<grid, THREADS, SMEM_BYTES>>>(
        x, W_ih, W_hh, b_ih, b_hh, W1, b1, W2, b2, out, B);
}

// round 11
// speedup vs baseline: 1.0979x; 1.0979x over previous
#include <cuda_runtime.h>
#include <cuda_bf16.h>
#include <cstdint>

// LSTM(I=13,H=64,T=5)+MLP(64->64 relu ->13), B=262144.
// Round 11: R9 (mma.sync bf16 hi/lo 3-product, 512 thr, 2-pass warp tile) with
// the epilogue rebuilt:
//  - gate-pair column layout [i0 f0 i1 f1 ...|g0 o0 g1 o1 ...] per 16-col block
//    puts all 4 gates of a neuron in ONE thread -> zero shfls.
//  - activations via tanh.approx.f32 (1 MUFU each): sig(x)=0.5+0.5*tanh(x/2).

#define THREADS 512
#define CTA_ROWS 128
#define WSTR 88   // halves per k-row (176B)
#define WSTR32 44
#define ZSTR 72
#define ZSTR32 36

// byte offsets in dynamic smem
#define OFF_WHI   0         // [256][88] bf16 : 45056
#define OFF_WLO   45056
#define OFF_AHI   90112     // [128][88] bf16 : 22528
#define OFF_ALO   112640
#define OFF_W1HI  135168    // [64][88] bf16  : 11264
#define OFF_W1LO  146432
#define OFF_W2HI  157696    // [16][88] bf16  : 2816
#define OFF_W2LO  160512
#define OFF_ZHI   163328    // [128][72] bf16 : 18432
#define OFF_ZLO   181760
#define OFF_BC    200192    // float [256]
#define OFF_B1    201216    // float [64]
#define OFF_B2    201472    // float [16]
#define SMEM_BYTES 201536

__device__ __forceinline__ void mma16816(float* d,
    uint32_t a0, uint32_t a1, uint32_t a2, uint32_t a3,
    uint32_t b0, uint32_t b1)
{
    asm volatile(
        "mma.sync.aligned.m16n8k16.row.col.f32.bf16.bf16.f32 "
        "{%0,%1,%2,%3}, {%4,%5,%6,%7}, {%8,%9}, {%0,%1,%2,%3};"
        : "+f"(d[0]), "+f"(d[1]), "+f"(d[2]), "+f"(d[3])
        : "r"(a0), "r"(a1), "r"(a2), "r"(a3), "r"(b0), "r"(b1));
}

__device__ __forceinline__ void bsplit(float v, unsigned short& h, unsigned short& l) {
    __nv_bfloat16 hb = __float2bfloat16(v);
    __nv_bfloat16 lb = __float2bfloat16(v - __bfloat162float(hb));
    h = __bfloat16_as_ushort(hb);
    l = __bfloat16_as_ushort(lb);
}

__device__ __forceinline__ float tanh_fast(float v) {
    float r; asm("tanh.approx.f32 %0, %1;" : "=f"(r) : "f"(v)); return r;
}
__device__ __forceinline__ float fsig(float v) {
    return fmaf(0.5f, tanh_fast(0.5f * v), 0.5f);
}

extern __shared__ char smem_raw[];

__global__ void __launch_bounds__(THREADS, 1)
lstm_hmma4_kernel(const float* __restrict__ x,
                  const float* __restrict__ W_ih,
                  const float* __restrict__ W_hh,
                  const float* __restrict__ b_ih,
                  const float* __restrict__ b_hh,
                  const float* __restrict__ W1,
                  const float* __restrict__ b1,
                  const float* __restrict__ W2,
                  const float* __restrict__ b2,
                  float* __restrict__ out,
                  int B)
{
    unsigned short* sW_hi  = (unsigned short*)(smem_raw + OFF_WHI);
    unsigned short* sW_lo  = (unsigned short*)(smem_raw + OFF_WLO);
    unsigned short* sA_hi  = (unsigned short*)(smem_raw + OFF_AHI);
    unsigned short* sA_lo  = (unsigned short*)(smem_raw + OFF_ALO);
    unsigned short* sW1_hi = (unsigned short*)(smem_raw + OFF_W1HI);
    unsigned short* sW1_lo = (unsigned short*)(smem_raw + OFF_W1LO);
    unsigned short* sW2_hi = (unsigned short*)(smem_raw + OFF_W2HI);
    unsigned short* sW2_lo = (unsigned short*)(smem_raw + OFF_W2LO);
    unsigned short* sZ_hi  = (unsigned short*)(smem_raw + OFF_ZHI);
    unsigned short* sZ_lo  = (unsigned short*)(smem_raw + OFF_ZLO);
    const uint32_t* W_hi32  = (const uint32_t*)sW_hi;
    const uint32_t* W_lo32  = (const uint32_t*)sW_lo;
    const uint32_t* A_hi32  = (const uint32_t*)sA_hi;
    const uint32_t* A_lo32  = (const uint32_t*)sA_lo;
    const uint32_t* W1_hi32 = (const uint32_t*)sW1_hi;
    const uint32_t* W1_lo32 = (const uint32_t*)sW1_lo;
    const uint32_t* W2_hi32 = (const uint32_t*)sW2_hi;
    const uint32_t* W2_lo32 = (const uint32_t*)sW2_lo;
    const uint32_t* Z_hi32  = (const uint32_t*)sZ_hi;
    const uint32_t* Z_lo32  = (const uint32_t*)sZ_lo;
    float* s_bc = (float*)(smem_raw + OFF_BC);
    float* s_b1 = (float*)(smem_raw + OFF_B1);
    float* s_b2 = (float*)(smem_raw + OFF_B2);

    const int tid  = threadIdx.x;
    const int lane = tid & 31;
    const int w    = tid >> 5;      // warp 0..15
    const int g    = lane >> 2;     // 0..7
    const int c    = lane & 3;      // 0..3
    const int rg   = w >> 3;        // row group 0..1 (64 rows each)
    const int cg   = w & 7;         // col group 0..7 (32 gate-cols each)
    const int b0   = blockIdx.x * CTA_ROWS;

    // ---------------- stage weights (bf16 hi/lo) ----------------
    // Column map: block b = C>>4 covers neurons 4b..4b+3.
    //   r = C&15; r<8: neuron 4b+(r>>1), gate = r&1 ? f : i
    //             r>=8: neuron 4b+((r-8)>>1), gate = r&1 ? o : g
    // Original row R = 64*gate + neuron.  (gate order in params: i,f,g,o)
    for (int idx = tid; idx < 256 * 80; idx += THREADS) {
        int C = idx / 80, k = idx % 80;
        int blk = C >> 4, r = C & 15;
        int neuron = 4 * blk + ((r & 7) >> 1);
        int gate = (r < 8) ? (r & 1) : 2 + (r & 1);
        int R = 64 * gate + neuron;
        float v = 0.0f;
        if (k < 64)      v = W_hh[R * 64 + k];
        else if (k < 77) v = W_ih[R * 13 + (k - 64)];
        unsigned short h, l; bsplit(v, h, l);
        sW_hi[C * WSTR + k] = h;
        sW_lo[C * WSTR + k] = l;
    }
    for (int idx = tid; idx < 64 * 64; idx += THREADS) {
        int j = idx >> 6, k = idx & 63;
        unsigned short h, l; bsplit(W1[j * 64 + k], h, l);
        sW1_hi[j * WSTR + k] = h;
        sW1_lo[j * WSTR + k] = l;
    }
    for (int idx = tid; idx < 16 * 64; idx += THREADS) {
        int p = idx >> 6, k = idx & 63;
        float v = (p < 13) ? W2[p * 64 + k] : 0.0f;
        unsigned short h, l; bsplit(v, h, l);
        sW2_hi[p * WSTR + k] = h;
        sW2_lo[p * WSTR + k] = l;
    }
    for (int idx = tid; idx < 256; idx += THREADS) {
        int blk = idx >> 4, r = idx & 15;
        int neuron = 4 * blk + ((r & 7) >> 1);
        int gate = (r < 8) ? (r & 1) : 2 + (r & 1);
        int R = 64 * gate + neuron;
        s_bc[idx] = b_ih[R] + b_hh[R];
    }
    if (tid < 64) s_b1[tid] = b1[tid];
    if (tid < 16) s_b2[tid] = (tid < 13) ? b2[tid] : 0.0f;

    // zero A arrays (h part = h0 = 0, pads stay 0)
    {
        uint32_t* Ah = (uint32_t*)sA_hi;
        uint32_t* Al = (uint32_t*)sA_lo;
        for (int idx = tid; idx < CTA_ROWS * WSTR32; idx += THREADS) {
            Ah[idx] = 0; Al[idx] = 0;
        }
    }
    __syncthreads();

    // x(t=0) into A at k = 64+i
    for (int idx = tid; idx < CTA_ROWS * 13; idx += THREADS) {
        int r = idx / 13, i = idx % 13;
        unsigned short h, l; bsplit(x[(size_t)(b0 + r) * 65 + i], h, l);
        sA_hi[r * WSTR + 64 + i] = h;
        sA_lo[r * WSTR + 64 + i] = l;
    }

    float creg[16];
#pragma unroll
    for (int i = 0; i < 16; i++) creg[i] = 0.0f;

    __syncthreads();

    // ---------------- 5 recurrent steps ----------------
#pragma unroll 1
    for (int t = 0; t < 5; t++) {
        // prefetch x(t+1)
        float xf[4];
        if (t < 4) {
#pragma unroll
            for (int s = 0; s < 4; s++) {
                int idx = tid + s * THREADS;
                if (idx < CTA_ROWS * 13) {
                    int r = idx / 13, i = idx % 13;
                    xf[s] = x[(size_t)(b0 + r) * 65 + (t + 1) * 13 + i];
                }
            }
        }

        float hv[16];   // index = p*8 + rt*2 + j(rowhalf)

#pragma unroll
        for (int p = 0; p < 2; p++) {
            float d[4][2][4];
#pragma unroll
            for (int ct = 0; ct < 2; ct++) {
                int C0 = 32 * cg + 16 * p + 8 * ct + 2 * c;
                float bx = s_bc[C0], by = s_bc[C0 + 1];
#pragma unroll
                for (int rt = 0; rt < 4; rt++) {
                    d[rt][ct][0] = bx; d[rt][ct][1] = by;
                    d[rt][ct][2] = bx; d[rt][ct][3] = by;
                }
            }

#pragma unroll
            for (int kc = 0; kc < 5; kc++) {
                uint32_t bh[2][2], bl[2][2];
#pragma unroll
                for (int ct = 0; ct < 2; ct++) {
                    int widx = (32 * cg + 16 * p + 8 * ct + g) * WSTR32 + 8 * kc + c;
                    bh[ct][0] = W_hi32[widx]; bh[ct][1] = W_hi32[widx + 4];
                    bl[ct][0] = W_lo32[widx]; bl[ct][1] = W_lo32[widx + 4];
                }
#pragma unroll
                for (int rt = 0; rt < 4; rt++) {
                    int r0w = (rg * 64 + 16 * rt + g) * WSTR32 + 8 * kc + c;
                    int r1w = r0w + 8 * WSTR32;
                    uint32_t ah0 = A_hi32[r0w],     ah1 = A_hi32[r1w];
                    uint32_t ah2 = A_hi32[r0w + 4], ah3 = A_hi32[r1w + 4];
                    uint32_t al0 = A_lo32[r0w],     al1 = A_lo32[r1w];
                    uint32_t al2 = A_lo32[r0w + 4], al3 = A_lo32[r1w + 4];
#pragma unroll
                    for (int ct = 0; ct < 2; ct++) {
                        mma16816(d[rt][ct], ah0, ah1, ah2, ah3, bh[ct][0], bh[ct][1]);
                        mma16816(d[rt][ct], ah0, ah1, ah2, ah3, bl[ct][0], bl[ct][1]);
                        mma16816(d[rt][ct], al0, al1, al2, al3, bh[ct][0], bh[ct][1]);
                    }
                }
            }

            // epilogue compute: all 4 gates of neuron (8cg+4p+c) are in-thread
#pragma unroll
            for (int rt = 0; rt < 4; rt++) {
#pragma unroll
                for (int j = 0; j < 2; j++) {
                    float gi = d[rt][0][2 * j], gf = d[rt][0][2 * j + 1];
                    float gg = d[rt][1][2 * j], go = d[rt][1][2 * j + 1];
                    int ci = p * 8 + rt * 2 + j;
                    float cn = fsig(gf) * creg[ci] + fsig(gi) * tanh_fast(gg);
                    creg[ci] = cn;
                    hv[ci] = fsig(go) * tanh_fast(cn);
                }
            }
        }

        __syncthreads();   // all A reads (both passes, all warps) complete

        // deferred h writes: row = rg*64+16rt+g+8j, neuron n = 8cg+4p+c
#pragma unroll
        for (int p = 0; p < 2; p++) {
#pragma unroll
            for (int rt = 0; rt < 4; rt++) {
#pragma unroll
                for (int j = 0; j < 2; j++) {
                    int row = rg * 64 + 16 * rt + g + 8 * j;
                    int n   = 8 * cg + 4 * p + c;
                    unsigned short h, l; bsplit(hv[p * 8 + rt * 2 + j], h, l);
                    sA_hi[row * WSTR + n] = h;
                    sA_lo[row * WSTR + n] = l;
                }
            }
        }
        if (t < 4) {
#pragma unroll
            for (int s = 0; s < 4; s++) {
                int idx = tid + s * THREADS;
                if (idx < CTA_ROWS * 13) {
                    int r = idx / 13, i = idx % 13;
                    unsigned short h, l; bsplit(xf[s], h, l);
                    sA_hi[r * WSTR + 64 + i] = h;
                    sA_lo[r * WSTR + 64 + i] = l;
                }
            }
        }
        __syncthreads();
    }

    // ---------------- MLP layer 1 via mma: z = relu(h @ W1^T + b1) ----------------
    {
        const int m_rg = w >> 3;     // 0..1 (64 rows)
        const int m_cg = w & 7;      // 0..7 (8 cols)
        int col0 = 8 * m_cg + 2 * c;
        float dz[4][4];
#pragma unroll
        for (int rt = 0; rt < 4; rt++) {
            dz[rt][0] = s_b1[col0]; dz[rt][1] = s_b1[col0 + 1];
            dz[rt][2] = s_b1[col0]; dz[rt][3] = s_b1[col0 + 1];
        }
#pragma unroll
        for (int kc = 0; kc < 4; kc++) {
            int widx = (8 * m_cg + g) * WSTR32 + 8 * kc + c;
            uint32_t b1h0 = W1_hi32[widx], b1h1 = W1_hi32[widx + 4];
            uint32_t b1l0 = W1_lo32[widx], b1l1 = W1_lo32[widx + 4];
#pragma unroll
            for (int rt = 0; rt < 4; rt++) {
                int r0w = (m_rg * 64 + 16 * rt + g) * WSTR32 + 8 * kc + c;
                int r1w = r0w + 8 * WSTR32;
                uint32_t ah0 = A_hi32[r0w],     ah1 = A_hi32[r1w];
                uint32_t ah2 = A_hi32[r0w + 4], ah3 = A_hi32[r1w + 4];
                uint32_t al0 = A_lo32[r0w],     al1 = A_lo32[r1w];
                uint32_t al2 = A_lo32[r0w + 4], al3 = A_lo32[r1w + 4];
                mma16816(dz[rt], ah0, ah1, ah2, ah3, b1h0, b1h1);
                mma16816(dz[rt], ah0, ah1, ah2, ah3, b1l0, b1l1);
                mma16816(dz[rt], al0, al1, al2, al3, b1h0, b1h1);
            }
        }
#pragma unroll
        for (int rt = 0; rt < 4; rt++) {
            int rA = m_rg * 64 + 16 * rt + g, rB = rA + 8;
            unsigned short h, l;
            bsplit(fmaxf(dz[rt][0], 0.0f), h, l);
            sZ_hi[rA * ZSTR + col0] = h;     sZ_lo[rA * ZSTR + col0] = l;
            bsplit(fmaxf(dz[rt][1], 0.0f), h, l);
            sZ_hi[rA * ZSTR + col0 + 1] = h; sZ_lo[rA * ZSTR + col0 + 1] = l;
            bsplit(fmaxf(dz[rt][2], 0.0f), h, l);
            sZ_hi[rB * ZSTR + col0] = h;     sZ_lo[rB * ZSTR + col0] = l;
            bsplit(fmaxf(dz[rt][3], 0.0f), h, l);
            sZ_hi[rB * ZSTR + col0 + 1] = h; sZ_lo[rB * ZSTR + col0 + 1] = l;
        }
    }
    __syncthreads();

    // ---------------- MLP layer 2 via mma: out = z @ W2^T + b2 ----------------
    {
        const int r2 = w >> 1;       // 0..7 (16 rows)
        const int c2 = w & 1;        // 0..1 (8 cols)
        int colA = 8 * c2 + 2 * c, colB = colA + 1;
        float dd[4];
        dd[0] = s_b2[colA]; dd[1] = s_b2[colB];
        dd[2] = s_b2[colA]; dd[3] = s_b2[colB];
#pragma unroll
        for (int kc = 0; kc < 4; kc++) {
            int widx = (8 * c2 + g) * WSTR32 + 8 * kc + c;
            uint32_t b2h0 = W2_hi32[widx], b2h1 = W2_hi32[widx + 4];
            uint32_t b2l0 = W2_lo32[widx], b2l1 = W2_lo32[widx + 4];
            int r0w = (16 * r2 + g) * ZSTR32 + 8 * kc + c;
            int r1w = r0w + 8 * ZSTR32;
            uint32_t ah0 = Z_hi32[r0w],     ah1 = Z_hi32[r1w];
            uint32_t ah2 = Z_hi32[r0w + 4], ah3 = Z_hi32[r1w + 4];
            uint32_t al0 = Z_lo32[r0w],     al1 = Z_lo32[r1w];
            uint32_t al2 = Z_lo32[r0w + 4], al3 = Z_lo32[r1w + 4];
            mma16816(dd, ah0, ah1, ah2, ah3, b2h0, b2h1);
            mma16816(dd, ah0, ah1, ah2, ah3, b2l0, b2l1);
            mma16816(dd, al0, al1, al2, al3, b2h0, b2h1);
        }
        int rowA = 16 * r2 + g, rowB = rowA + 8;
        if (colA < 13) {
            out[(size_t)(b0 + rowA) * 13 + colA] = dd[0];
            out[(size_t)(b0 + rowB) * 13 + colA] = dd[2];
        }
        if (colB < 13) {
            out[(size_t)(b0 + rowA) * 13 + colB] = dd[1];
            out[(size_t)(b0 + rowB) * 13 + colB] = dd[3];
        }
    }
}

extern "C" void kernel_launch(void* const* d_in, const int* in_sizes, int n_in,
                              void* d_out, int out_size)
{
    const float* x    = (const float*)d_in[0];
    const float* W_ih = (const float*)d_in[1];
    const float* W_hh = (const float*)d_in[2];
    const float* b_ih = (const float*)d_in[3];
    const float* b_hh = (const float*)d_in[4];
    const float* W1   = (const float*)d_in[5];
    const float* b1   = (const float*)d_in[6];
    const float* W2   = (const float*)d_in[7];
    const float* b2   = (const float*)d_in[8];
    float* out = (float*)d_out;

    const int B = in_sizes[0] / 65;

    cudaFuncSetAttribute(lstm_hmma4_kernel,
                         cudaFuncAttributeMaxDynamicSharedMemorySize, SMEM_BYTES);

    const int grid = B / CTA_ROWS;
    lstm_hmma4_kernel<<<grid, THREADS, SMEM_BYTES>>>(
        x, W_ih, W_hh, b_ih, b_hh, W1, b1, W2, b2, out, B);
}